// round 9
// baseline (speedup 1.0000x reference)
#include <cuda_runtime.h>
#include <cstdint>

// ---------------------------------------------------------------------------
// SPELL forward, algebraically collapsed:
//   per node:  a[4] = feat128 . Wa + x4 . Sa + Ta[spk_idx] + Ca   (face cols 0,1; body cols 2,3)
//              b[4] = feat128 . Wb + x4 . Sb + Tb[spk_idx] + Cb
//   per edge:  m[dst] = max(m[dst], b[src])          (4 channels, ordered-uint atomicMax)
//   output:    out[i] = hasEdge ? (a_f + m_f) + (a_b + m_b) : 0
// ---------------------------------------------------------------------------

#define MAXN   50176
#define D_IN   901
#define INITU  0x007fffffu   // f2u(-inf)

__device__ float  g_Wa[512];   // [col][k]  col = fam*2 + c, k<128  (layout col*128+k)
__device__ float  g_Wb[512];
__device__ float  g_Sa[16];    // col*4 + t
__device__ float  g_Sb[16];
__device__ float  g_Ta[12];    // col*3 + r
__device__ float  g_Tb[12];
__device__ float  g_Ca[4];
__device__ float  g_Cb[4];
__device__ float4 g_a[MAXN];
__device__ float4 g_b[MAXN];
__device__ uint4  g_m[MAXN];

__device__ __forceinline__ unsigned f2u(float f) {
    unsigned u = __float_as_uint(f);
    return (u & 0x80000000u) ? ~u : (u | 0x80000000u);
}
__device__ __forceinline__ float u2f(unsigned u) {
    unsigned v = (u & 0x80000000u) ? (u & 0x7fffffffu) : ~u;
    return __uint_as_float(v);
}

// ---------------------------------------------------------------------------
// Precompute composed weights. grid=2 (blockIdx.x = fam), 256 threads.
// ---------------------------------------------------------------------------
__global__ void __launch_bounds__(256, 1) precompute_kernel(
    const float* __restrict__ spkw, const float* __restrict__ spkb,
    const float* __restrict__ spaw, const float* __restrict__ spab,
    const float* __restrict__ f1w,  const float* __restrict__ f1b,
    const float* __restrict__ f2w,  const float* __restrict__ f2b,
    const float* __restrict__ few,  const float* __restrict__ feb,
    const float* __restrict__ g1w,  const float* __restrict__ g1b,
    const float* __restrict__ g2w,  const float* __restrict__ g2b,
    const float* __restrict__ gew,  const float* __restrict__ geb)
{
    int fam = blockIdx.x;
    int tid = threadIdx.x;
    const float* w1 = fam ? g1w : f1w;
    const float* b1 = fam ? g1b : f1b;
    const float* w2 = fam ? g2w : f2w;
    const float* b2 = fam ? g2b : f2b;
    const float* we = fam ? gew : few;
    const float* eb = fam ? geb : feb;

    __shared__ float s_wea[2][64], s_web[2][64];       // [c][j]
    __shared__ float s_Pa[2][2][16], s_Pb[2][2][16];   // [which][c][s]  which: 0=spk 1=spa

    if (tid < 128) {
        int j = tid >> 1, c = tid & 1;
        float wb = we[(64 + j) * 2 + c];
        s_web[c][j] = wb;
        s_wea[c][j] = we[j * 2 + c] - wb;
    }
    __syncthreads();

    // main composed weight: (k,c) per thread, 64-iter j loop
    {
        int k = tid >> 1, c = tid & 1;
        float sa = 0.f, sb = 0.f;
        for (int j = 0; j < 64; j++) {
            float wk = w1[k * 64 + j] + w2[k * 64 + j];
            sa += wk * s_wea[c][j];
            sb += wk * s_web[c][j];
        }
        int col = fam * 2 + c;
        g_Wa[col * 128 + k] = sa;
        g_Wb[col * 128 + k] = sb;
    }

    // P intermediates: 64 tasks (which, c, s), 64-iter j loop each
    if (tid < 64) {
        int which = tid & 1, c = (tid >> 1) & 1, s = tid >> 2;
        int row = which ? (144 + s) : (128 + s);
        float pa = 0.f, pb = 0.f;
        for (int j = 0; j < 64; j++) {
            float v = w2[row * 64 + j];
            pa += v * s_wea[c][j];
            pb += v * s_web[c][j];
        }
        s_Pa[which][c][s] = pa;
        s_Pb[which][c][s] = pb;
    }
    __syncthreads();

    // spatial table Sa/Sb [col][t]: 8 tasks, 16-iter loop
    if (tid < 8) {
        int t = tid >> 1, c = tid & 1;
        float sA = 0.f, sB = 0.f;
        for (int s = 0; s < 16; s++) {
            float sw = spaw[t * 16 + s];
            sA += sw * s_Pa[1][c][s];
            sB += sw * s_Pb[1][c][s];
        }
        int col = fam * 2 + c;
        g_Sa[col * 4 + t] = sA;
        g_Sb[col * 4 + t] = sB;
    }

    // speaker table Ta/Tb [col][r]: 6 tasks, 16-iter loop
    if (tid >= 32 && tid < 38) {
        int t2 = tid - 32;
        int rr = t2 >> 1, c = t2 & 1;
        float sA = 0.f, sB = 0.f;
        for (int s = 0; s < 16; s++) {
            float sw = spkw[rr * 16 + s] + spkb[s];
            sA += sw * s_Pa[0][c][s];
            sB += sw * s_Pb[0][c][s];
        }
        int col = fam * 2 + c;
        g_Ta[col * 3 + rr] = sA;
        g_Tb[col * 3 + rr] = sB;
    }

    // constant terms Ca/Cb [col]: 2 tasks
    if (tid >= 64 && tid < 66) {
        int c = tid - 64;
        float cA = eb[c], cB = 0.f;
        for (int j = 0; j < 64; j++) {
            float bj = b1[j] + b2[j];
            cA += bj * s_wea[c][j];
            cB += bj * s_web[c][j];
        }
        for (int s = 0; s < 16; s++) {
            float sb = spab[s];
            cA += sb * s_Pa[1][c][s];
            cB += sb * s_Pb[1][c][s];
        }
        int col = fam * 2 + c;
        g_Ca[col] = cA;
        g_Cb[col] = cB;
    }
}

// ---------------------------------------------------------------------------
// Node kernel: one warp per node; float4 loads (lane l covers cols 4l..4l+3
// and 128+4l..+3); float4 shared-weight reads; 8-way warp reduction.
// ---------------------------------------------------------------------------
__global__ void __launch_bounds__(256) node_kernel(const float* __restrict__ x, int N)
{
    __shared__ float4 sWa[128];   // [col][k/4] as float4, col*32 + k4
    __shared__ float4 sWb[128];
    for (int i = threadIdx.x; i < 128; i += 256) {
        sWa[i] = ((const float4*)g_Wa)[i];
        sWb[i] = ((const float4*)g_Wb)[i];
    }
    __syncthreads();

    int warp = threadIdx.x >> 5;
    int lane = threadIdx.x & 31;
    int node = blockIdx.x * 8 + warp;
    if (node >= N) return;

    const float* row = x + (size_t)node * D_IN;

    // tail columns (896..900) read by lanes 0..4 in parallel, broadcast later
    float tailv = (lane < 5) ? __ldg(row + 896 + lane) : 0.f;

    // row is 901 floats; rows alternate 16B alignment. Use ldg on float4 only
    // when aligned, else scalar fallback (node parity decides, warp-uniform).
    float4 vf, vb;
    if ((((uintptr_t)row) & 15) == 0) {
        vf = __ldg((const float4*)row + lane);
        vb = __ldg((const float4*)row + 32 + lane);
    } else {
        vf.x = __ldg(row + 4 * lane + 0);
        vf.y = __ldg(row + 4 * lane + 1);
        vf.z = __ldg(row + 4 * lane + 2);
        vf.w = __ldg(row + 4 * lane + 3);
        vb.x = __ldg(row + 128 + 4 * lane + 0);
        vb.y = __ldg(row + 128 + 4 * lane + 1);
        vb.z = __ldg(row + 128 + 4 * lane + 2);
        vb.w = __ldg(row + 128 + 4 * lane + 3);
    }

    float sA[4], sB[4];
#pragma unroll
    for (int c = 0; c < 2; c++) {
        float4 wa = sWa[c * 32 + lane];
        float4 wb = sWb[c * 32 + lane];
        sA[c] = vf.x * wa.x + vf.y * wa.y + vf.z * wa.z + vf.w * wa.w;
        sB[c] = vf.x * wb.x + vf.y * wb.y + vf.z * wb.z + vf.w * wb.w;
    }
#pragma unroll
    for (int c = 2; c < 4; c++) {
        float4 wa = sWa[c * 32 + lane];
        float4 wb = sWb[c * 32 + lane];
        sA[c] = vb.x * wa.x + vb.y * wa.y + vb.z * wa.z + vb.w * wa.w;
        sB[c] = vb.x * wb.x + vb.y * wb.y + vb.z * wb.z + vb.w * wb.w;
    }
#pragma unroll
    for (int off = 16; off; off >>= 1) {
#pragma unroll
        for (int c = 0; c < 4; c++) {
            sA[c] += __shfl_xor_sync(0xffffffffu, sA[c], off);
            sB[c] += __shfl_xor_sync(0xffffffffu, sB[c], off);
        }
    }
    float t0  = __shfl_sync(0xffffffffu, tailv, 0);
    float t1  = __shfl_sync(0xffffffffu, tailv, 1);
    float t2  = __shfl_sync(0xffffffffu, tailv, 2);
    float t3  = __shfl_sync(0xffffffffu, tailv, 3);
    float cnt = __shfl_sync(0xffffffffu, tailv, 4);
    if (lane == 0) {
        int idx = (int)cnt - 1;
        if (idx < 0) idx = 0;
        if (idx > 2) idx = 2;
        float av[4], bv[4];
#pragma unroll
        for (int c = 0; c < 4; c++) {
            av[c] = sA[c] + t0 * g_Sa[c * 4 + 0] + t1 * g_Sa[c * 4 + 1]
                          + t2 * g_Sa[c * 4 + 2] + t3 * g_Sa[c * 4 + 3]
                          + g_Ta[c * 3 + idx] + g_Ca[c];
            bv[c] = sB[c] + t0 * g_Sb[c * 4 + 0] + t1 * g_Sb[c * 4 + 1]
                          + t2 * g_Sb[c * 4 + 2] + t3 * g_Sb[c * 4 + 3]
                          + g_Tb[c * 3 + idx] + g_Cb[c];
        }
        g_a[node] = make_float4(av[0], av[1], av[2], av[3]);
        g_b[node] = make_float4(bv[0], bv[1], bv[2], bv[3]);
        g_m[node] = make_uint4(INITU, INITU, INITU, INITU);
    }
}

// ---------------------------------------------------------------------------
// Edge kernel: 4 edges per thread via int4 index loads (MLP=4 gathers);
// read-before-atomic filter, then RED.MAX into m[dst].
// ---------------------------------------------------------------------------
__device__ __forceinline__ void edge_one(int attr, int src, int dst)
{
    if (attr != 111 && attr != 0) return;
    float4 bv = g_b[src];
    unsigned u0 = f2u(bv.x), u1 = f2u(bv.y), u2 = f2u(bv.z), u3 = f2u(bv.w);
    uint4 cur = *(const uint4*)&g_m[dst];   // non-atomic peek (monotone, safe)
    unsigned* m = (unsigned*)&g_m[dst];
    if (u0 > cur.x) atomicMax(m + 0, u0);
    if (u1 > cur.y) atomicMax(m + 1, u1);
    if (u2 > cur.z) atomicMax(m + 2, u2);
    if (u3 > cur.w) atomicMax(m + 3, u3);
}

__global__ void __launch_bounds__(256) edge_kernel(
    const int* __restrict__ ei, const int* __restrict__ ea, int E)
{
    int t = blockIdx.x * blockDim.x + threadIdx.x;
    int e = t * 4;
    if (e >= E) return;
    if (e + 3 < E) {
        int4 attr = *(const int4*)(ea + e);
        int4 s4   = *(const int4*)(ei + e);
        int4 d4   = *(const int4*)(ei + E + e);
        edge_one(attr.x, s4.x, d4.x);
        edge_one(attr.y, s4.y, d4.y);
        edge_one(attr.z, s4.z, d4.z);
        edge_one(attr.w, s4.w, d4.w);
    } else {
        for (int i = e; i < E; i++)
            edge_one(ea[i], ei[i], ei[E + i]);
    }
}

// ---------------------------------------------------------------------------
// Output kernel: combine face+body; empty segments -> 0.
// ---------------------------------------------------------------------------
__global__ void __launch_bounds__(256) out_kernel(float* __restrict__ out, int N)
{
    int i = blockIdx.x * blockDim.x + threadIdx.x;
    if (i >= N) return;
    uint4 mu = g_m[i];
    float2 o;
    if (mu.x == INITU) {
        o.x = 0.f;
        o.y = 0.f;
    } else {
        float4 a = g_a[i];
        o.x = (a.x + u2f(mu.x)) + (a.z + u2f(mu.z));
        o.y = (a.y + u2f(mu.y)) + (a.w + u2f(mu.w));
    }
    ((float2*)out)[i] = o;
}

extern "C" void kernel_launch(void* const* d_in, const int* in_sizes, int n_in,
                              void* d_out, int out_size)
{
    const float* x    = (const float*)d_in[0];
    const int*   ei   = (const int*)d_in[1];
    const int*   ea   = (const int*)d_in[2];
    const float* spkw = (const float*)d_in[3];
    const float* spkb = (const float*)d_in[4];
    const float* spaw = (const float*)d_in[5];
    const float* spab = (const float*)d_in[6];
    const float* f1w  = (const float*)d_in[7];
    const float* f1b  = (const float*)d_in[8];
    const float* f2w  = (const float*)d_in[9];
    const float* f2b  = (const float*)d_in[10];
    const float* few  = (const float*)d_in[11];
    const float* feb  = (const float*)d_in[12];
    const float* g1w  = (const float*)d_in[13];
    const float* g1b  = (const float*)d_in[14];
    const float* g2w  = (const float*)d_in[15];
    const float* g2b  = (const float*)d_in[16];
    const float* gew  = (const float*)d_in[17];
    const float* geb  = (const float*)d_in[18];

    int N = in_sizes[0] / D_IN;
    int E = in_sizes[2];

    precompute_kernel<<<2, 256>>>(spkw, spkb, spaw, spab,
                                  f1w, f1b, f2w, f2b, few, feb,
                                  g1w, g1b, g2w, g2b, gew, geb);
    node_kernel<<<(N + 7) / 8, 256>>>(x, N);
    int nt = (E + 3) / 4;
    edge_kernel<<<(nt + 255) / 256, 256>>>(ei, ea, E);
    out_kernel<<<(N + 255) / 256, 256>>>((float*)d_out, N);
}